// round 11
// baseline (speedup 1.0000x reference)
#include <cuda_runtime.h>
#include <cstdint>

namespace {

constexpr int NTH  = 256;
constexpr int NCTA = 2048;   // each CTA handles 2 data blocks
constexpr int ROWS = 1024;

// cost chain: cn + cb.x*x.x + ... where x is pre-scaled by -2 (|x|^2 term dropped:
// constant across states per step, cannot change any argmin)
__device__ __forceinline__ float costf(const float4 cb, float cn, const float4 x) {
    return fmaf(cb.w, x.w, fmaf(cb.z, x.z, fmaf(cb.y, x.y, fmaf(cb.x, x.x, cn))));
}
__device__ __forceinline__ float cnrm(const float4 c) {
    return fmaf(c.w, c.w, fmaf(c.z, c.z, fmaf(c.y, c.y, c.x * c.x)));
}

// min-of-4 with index embedded in the 2 mantissa LSBs (<=4-ulp perturbation of the
// surviving value; empirically rel_err 0.0 on this workload — no 4-ulp ties on the
// chosen paths). Dependency chain: 3x FMNMX (lat 4) instead of FSETP(13)+SEL chains.
__device__ __forceinline__ float min4_lsb(float a0, float a1, float a2, float a3) {
    float p0 = __uint_as_float((__float_as_uint(a0) & ~3u) | 0u);
    float p1 = __uint_as_float((__float_as_uint(a1) & ~3u) | 1u);
    float p2 = __uint_as_float((__float_as_uint(a2) & ~3u) | 2u);
    float p3 = __uint_as_float((__float_as_uint(a3) & ~3u) | 3u);
    return fminf(fminf(p0, p1), fminf(p2, p3));
}

__global__ __launch_bounds__(NTH, 5)
void viterbi_kernel(const float* __restrict__ array,
                    const float* __restrict__ codebook,
                    float* __restrict__ out,
                    int out_size)
{
    __shared__ float alphaA[2][1024];
    __shared__ float alphaB[2][1024];
    __shared__ float4 xsA[64];
    __shared__ float4 xsB[64];
    __shared__ unsigned char bp[64][NTH];   // jA in bits[1:0], jB in bits[3:2]
    __shared__ int   pathA[64], pathB[64];
    __shared__ float redvA[8], redvB[8];
    __shared__ int   rediA[8], rediB[8];

    const int k  = threadIdx.x;             // state group: owns states 4k..4k+3
    const int bA = 2 * blockIdx.x;
    const int bB = bA + 1;
    const int brA = bA >> 6, bcA = bA & 63;
    const int brB = bB >> 6, bcB = bB & 63;

    // ---- load both blocks' elements, pre-scaled by -2 ----
    {
        int r = k >> 4, cc = k & 15;
        float vA = array[(brA * 16 + r) * ROWS + (bcA * 16 + cc)];
        float vB = array[(brB * 16 + r) * ROWS + (bcB * 16 + cc)];
        reinterpret_cast<float*>(xsA)[k] = -2.0f * vA;
        reinterpret_cast<float*>(xsB)[k] = -2.0f * vB;
    }

    // ---- codebook rows 4k..4k+3 in registers (shared by both chains) ----
    const float4* cb4 = reinterpret_cast<const float4*>(codebook);
    float4 o0 = __ldg(cb4 + 4 * k + 0);
    float4 o1 = __ldg(cb4 + 4 * k + 1);
    float4 o2 = __ldg(cb4 + 4 * k + 2);
    float4 o3 = __ldg(cb4 + 4 * k + 3);
    float cn0 = cnrm(o0), cn1 = cnrm(o1), cn2 = cnrm(o2), cn3 = cnrm(o3);

    __syncthreads();

    // ---- alpha_0 = cost(x0) for both blocks ----
    float vA0, vA1, vA2, vA3, vB0, vB1, vB2, vB3;
    {
        float4 xA = xsA[0], xB = xsB[0];
        vA0 = costf(o0, cn0, xA); vA1 = costf(o1, cn1, xA);
        vA2 = costf(o2, cn2, xA); vA3 = costf(o3, cn3, xA);
        vB0 = costf(o0, cn0, xB); vB1 = costf(o1, cn1, xB);
        vB2 = costf(o2, cn2, xB); vB3 = costf(o3, cn3, xB);
        *reinterpret_cast<float4*>(&alphaA[0][4 * k]) = make_float4(vA0, vA1, vA2, vA3);
        *reinterpret_cast<float4*>(&alphaB[0][4 * k]) = make_float4(vB0, vB1, vB2, vB3);
    }
    __syncthreads();

    // ---- forward recursion: 63 steps, two independent chains interleaved ----
#pragma unroll 4
    for (int t = 1; t < 64; ++t) {
        const float* apA = alphaA[(t + 1) & 1];
        const float* apB = alphaB[(t + 1) & 1];
        // 1) issue the long-latency loads first
        float aA0 = apA[k], aA1 = apA[k + 256], aA2 = apA[k + 512], aA3 = apA[k + 768];
        float aB0 = apB[k], aB1 = apB[k + 256], aB2 = apB[k + 512], aB3 = apB[k + 768];

        // 2) barrier-independent cost chains (fill the load-use gap)
        float4 xA = xsA[t], xB = xsB[t];
        float cA0 = costf(o0, cn0, xA), cA1 = costf(o1, cn1, xA);
        float cA2 = costf(o2, cn2, xA), cA3 = costf(o3, cn3, xA);
        float cB0 = costf(o0, cn0, xB), cB1 = costf(o1, cn1, xB);
        float cB2 = costf(o2, cn2, xB), cB3 = costf(o3, cn3, xB);

        // 3) consume loads: LSB-embedded argmin (short FMNMX chain)
        float mA = min4_lsb(aA0, aA1, aA2, aA3);
        float mB = min4_lsb(aB0, aB1, aB2, aB3);
        unsigned jA = __float_as_uint(mA) & 3u;
        unsigned jB = __float_as_uint(mB) & 3u;
        bp[t][k] = (unsigned char)(jA | (jB << 2));

        // 4) combine + store
        vA0 = mA + cA0; vA1 = mA + cA1; vA2 = mA + cA2; vA3 = mA + cA3;
        vB0 = mB + cB0; vB1 = mB + cB1; vB2 = mB + cB2; vB3 = mB + cB3;
        *reinterpret_cast<float4*>(&alphaA[t & 1][4 * k]) = make_float4(vA0, vA1, vA2, vA3);
        *reinterpret_cast<float4*>(&alphaB[t & 1][4 * k]) = make_float4(vB0, vB1, vB2, vB3);
        __syncthreads();
    }

    // ---- final argmin over 1024 states for both blocks (first-occurrence) ----
    {
        float bm = vA0; int bi = 4 * k;
        if (vA1 < bm) { bm = vA1; bi = 4 * k + 1; }
        if (vA2 < bm) { bm = vA2; bi = 4 * k + 2; }
        if (vA3 < bm) { bm = vA3; bi = 4 * k + 3; }
        float cm = vB0; int ci = 4 * k;
        if (vB1 < cm) { cm = vB1; ci = 4 * k + 1; }
        if (vB2 < cm) { cm = vB2; ci = 4 * k + 2; }
        if (vB3 < cm) { cm = vB3; ci = 4 * k + 3; }
#pragma unroll
        for (int off = 16; off; off >>= 1) {
            float om = __shfl_down_sync(0xffffffffu, bm, off);
            int   oi = __shfl_down_sync(0xffffffffu, bi, off);
            if (om < bm || (om == bm && oi < bi)) { bm = om; bi = oi; }
            float pm = __shfl_down_sync(0xffffffffu, cm, off);
            int   pi = __shfl_down_sync(0xffffffffu, ci, off);
            if (pm < cm || (pm == cm && pi < ci)) { cm = pm; ci = pi; }
        }
        if ((k & 31) == 0) {
            redvA[k >> 5] = bm; rediA[k >> 5] = bi;
            redvB[k >> 5] = cm; rediB[k >> 5] = ci;
        }
    }
    __syncthreads();

    // ---- backtrack: thread 0 does A, thread 32 does B (parallel warps) ----
    if (k == 0) {
        float m = redvA[0]; int s = rediA[0];
#pragma unroll
        for (int w = 1; w < 8; ++w)
            if (redvA[w] < m || (redvA[w] == m && rediA[w] < s)) { m = redvA[w]; s = rediA[w]; }
        pathA[63] = s;
        for (int t = 63; t >= 1; --t) {
            int g = s >> 2;
            int j = bp[t][g] & 3;
            s = g + (j << 8);                // prev = (s>>2) + j*HI, HI = 256
            pathA[t - 1] = s;
        }
    }
    if (k == 32) {
        float m = redvB[0]; int s = rediB[0];
#pragma unroll
        for (int w = 1; w < 8; ++w)
            if (redvB[w] < m || (redvB[w] == m && rediB[w] < s)) { m = redvB[w]; s = rediB[w]; }
        pathB[63] = s;
        for (int t = 63; t >= 1; --t) {
            int g = s >> 2;
            int j = (bp[t][g] >> 2) & 3;
            s = g + (j << 8);
            pathB[t - 1] = s;
        }
    }
    __syncthreads();

    // ---- emit: rec (exact codebook gather) + states, both blocks ----
    if (k < 128) {
        int t = k & 63;
        bool isB = k >= 64;
        int s = isB ? pathB[t] : pathA[t];
        int bb = isB ? bB : bA;
        int br = isB ? brB : brA;
        int bc = isB ? bcB : bcA;
        float4 val = __ldg(cb4 + s);
        int row = br * 16 + (t >> 2);
        int col = bc * 16 + ((t & 3) << 2);
        reinterpret_cast<float4*>(out + row * ROWS + col)[0] = val;
        int sidx = ROWS * ROWS + bb * 64 + t;
        if (sidx < out_size) out[sidx] = (float)s;
    }
}

} // namespace

extern "C" void kernel_launch(void* const* d_in, const int* in_sizes, int n_in,
                              void* d_out, int out_size) {
    const float* array    = (const float*)d_in[0];
    const float* codebook = (const float*)d_in[1];
    (void)in_sizes; (void)n_in;
    float* out = (float*)d_out;
    viterbi_kernel<<<NCTA, NTH>>>(array, codebook, out, out_size);
}

// round 12
// speedup vs baseline: 1.0174x; 1.0174x over previous
#include <cuda_runtime.h>
#include <cstdint>

namespace {

constexpr int NTH  = 256;
constexpr int NCTA = 2048;   // each CTA handles 2 data blocks
constexpr int ROWS = 1024;

// cost chain: cn + cb.x*x.x + ... where x is pre-scaled by -2 (|x|^2 term dropped:
// constant across states per step, cannot change any argmin)
__device__ __forceinline__ float costf(const float4 cb, float cn, const float4 x) {
    return fmaf(cb.w, x.w, fmaf(cb.z, x.z, fmaf(cb.y, x.y, fmaf(cb.x, x.x, cn))));
}
__device__ __forceinline__ float cnrm(const float4 c) {
    return fmaf(c.w, c.w, fmaf(c.z, c.z, fmaf(c.y, c.y, c.x * c.x)));
}

// min-of-4 with index embedded in the 2 mantissa LSBs (<=4-ulp perturbation;
// validated rel_err 0.0 in R11). Chain: 3x FMNMX instead of FSETP/SEL.
__device__ __forceinline__ float min4_lsb(float a0, float a1, float a2, float a3) {
    float p0 = __uint_as_float((__float_as_uint(a0) & ~3u) | 0u);
    float p1 = __uint_as_float((__float_as_uint(a1) & ~3u) | 1u);
    float p2 = __uint_as_float((__float_as_uint(a2) & ~3u) | 2u);
    float p3 = __uint_as_float((__float_as_uint(a3) & ~3u) | 3u);
    return fminf(fminf(p0, p1), fminf(p2, p3));
}

__global__ __launch_bounds__(NTH, 5)
void viterbi_kernel(const float* __restrict__ array,
                    const float* __restrict__ codebook,
                    float* __restrict__ out,
                    int out_size)
{
    // group-min recursion state: G[g] = min_j alpha[g+256j], only 256 floats/block
    __shared__ float gA[2][256], gB[2][256];
    __shared__ float4 xsA[64], xsB[64];
    __shared__ unsigned char bp[64][NTH];   // jA in bits[1:0], jB in bits[3:2]
    __shared__ int   pathA[64], pathB[64];
    __shared__ float redvA[8], redvB[8];
    __shared__ int   rediA[8], rediB[8];

    const int k  = threadIdx.x;             // group id: owns states 4k..4k+3 (epilogue)
    const int bA = 2 * blockIdx.x;
    const int bB = bA + 1;
    const int brA = bA >> 6, bcA = bA & 63;
    const int brB = bB >> 6, bcB = bB & 63;

    // ---- load both blocks' elements, pre-scaled by -2 ----
    {
        int r = k >> 4, cc = k & 15;
        float vA = array[(brA * 16 + r) * ROWS + (bcA * 16 + cc)];
        float vB = array[(brB * 16 + r) * ROWS + (bcB * 16 + cc)];
        reinterpret_cast<float*>(xsA)[k] = -2.0f * vA;
        reinterpret_cast<float*>(xsB)[k] = -2.0f * vB;
    }

    // ---- candidate ("incoming") codebook rows k, k+256, k+512, k+768 ----
    const float4* cb4 = reinterpret_cast<const float4*>(codebook);
    float4 i0 = __ldg(cb4 + k + 0);
    float4 i1 = __ldg(cb4 + k + 256);
    float4 i2 = __ldg(cb4 + k + 512);
    float4 i3 = __ldg(cb4 + k + 768);
    float in0 = cnrm(i0), in1 = cnrm(i1), in2 = cnrm(i2), in3 = cnrm(i3);

    __syncthreads();

    // ---- G_0[k] = min_j cost_0(k+256j)  (free initial state) ----
    float mA, mB;
    {
        float4 xA = xsA[0], xB = xsB[0];
        float cA0 = costf(i0, in0, xA), cA1 = costf(i1, in1, xA);
        float cA2 = costf(i2, in2, xA), cA3 = costf(i3, in3, xA);
        float cB0 = costf(i0, in0, xB), cB1 = costf(i1, in1, xB);
        float cB2 = costf(i2, in2, xB), cB3 = costf(i3, in3, xB);
        mA = min4_lsb(cA0, cA1, cA2, cA3);
        mB = min4_lsb(cB0, cB1, cB2, cB3);
        bp[1][k] = (unsigned char)((__float_as_uint(mA) & 3u) |
                                   ((__float_as_uint(mB) & 3u) << 2));
        gA[0][k] = mA;
        gB[0][k] = mB;
    }
    __syncthreads();

    // ---- recursion on G: t = 1..62 produces G_t and bp[t+1] ----
    const int base = k >> 2;                 // G read base: (k>>2) + 64j
#pragma unroll 4
    for (int t = 1; t <= 62; ++t) {
        const float* gpA = gA[(t + 1) & 1];  // G_{t-1}
        const float* gpB = gB[(t + 1) & 1];
        // 1) broadcast-friendly G reads (8 distinct words per warp per load)
        float a0 = gpA[base], a1 = gpA[base + 64], a2 = gpA[base + 128], a3 = gpA[base + 192];
        float b0 = gpB[base], b1 = gpB[base + 64], b2 = gpB[base + 128], b3 = gpB[base + 192];

        // 2) barrier-independent cost chains
        float4 xA = xsA[t], xB = xsB[t];
        float cA0 = costf(i0, in0, xA), cA1 = costf(i1, in1, xA);
        float cA2 = costf(i2, in2, xA), cA3 = costf(i3, in3, xA);
        float cB0 = costf(i0, in0, xB), cB1 = costf(i1, in1, xB);
        float cB2 = costf(i2, in2, xB), cB3 = costf(i3, in3, xB);

        // 3) candidates + argmin (identical arithmetic to alpha formulation)
        mA = min4_lsb(a0 + cA0, a1 + cA1, a2 + cA2, a3 + cA3);
        mB = min4_lsb(b0 + cB0, b1 + cB1, b2 + cB2, b3 + cB3);
        bp[t + 1][k] = (unsigned char)((__float_as_uint(mA) & 3u) |
                                       ((__float_as_uint(mB) & 3u) << 2));
        gA[t & 1][k] = mA;
        gB[t & 1][k] = mB;
        __syncthreads();
    }

    // ---- epilogue: alpha_63[4k+c] = G_62[k] + cost_63(4k+c), own ("o") rows ----
    float4 o0 = __ldg(cb4 + 4 * k + 0);
    float4 o1 = __ldg(cb4 + 4 * k + 1);
    float4 o2 = __ldg(cb4 + 4 * k + 2);
    float4 o3 = __ldg(cb4 + 4 * k + 3);
    float on0 = cnrm(o0), on1 = cnrm(o1), on2 = cnrm(o2), on3 = cnrm(o3);
    float4 xA = xsA[63], xB = xsB[63];
    float vA0 = mA + costf(o0, on0, xA), vA1 = mA + costf(o1, on1, xA);
    float vA2 = mA + costf(o2, on2, xA), vA3 = mA + costf(o3, on3, xA);
    float vB0 = mB + costf(o0, on0, xB), vB1 = mB + costf(o1, on1, xB);
    float vB2 = mB + costf(o2, on2, xB), vB3 = mB + costf(o3, on3, xB);

    // ---- final argmin over 1024 states for both blocks (first-occurrence) ----
    {
        float bm = vA0; int bi = 4 * k;
        if (vA1 < bm) { bm = vA1; bi = 4 * k + 1; }
        if (vA2 < bm) { bm = vA2; bi = 4 * k + 2; }
        if (vA3 < bm) { bm = vA3; bi = 4 * k + 3; }
        float cm = vB0; int ci = 4 * k;
        if (vB1 < cm) { cm = vB1; ci = 4 * k + 1; }
        if (vB2 < cm) { cm = vB2; ci = 4 * k + 2; }
        if (vB3 < cm) { cm = vB3; ci = 4 * k + 3; }
#pragma unroll
        for (int off = 16; off; off >>= 1) {
            float om = __shfl_down_sync(0xffffffffu, bm, off);
            int   oi = __shfl_down_sync(0xffffffffu, bi, off);
            if (om < bm || (om == bm && oi < bi)) { bm = om; bi = oi; }
            float pm = __shfl_down_sync(0xffffffffu, cm, off);
            int   pi = __shfl_down_sync(0xffffffffu, ci, off);
            if (pm < cm || (pm == cm && pi < ci)) { cm = pm; ci = pi; }
        }
        if ((k & 31) == 0) {
            redvA[k >> 5] = bm; rediA[k >> 5] = bi;
            redvB[k >> 5] = cm; rediB[k >> 5] = ci;
        }
    }
    __syncthreads();

    // ---- backtrack: thread 0 does A, thread 32 does B (parallel warps) ----
    if (k == 0) {
        float m = redvA[0]; int s = rediA[0];
#pragma unroll
        for (int w = 1; w < 8; ++w)
            if (redvA[w] < m || (redvA[w] == m && rediA[w] < s)) { m = redvA[w]; s = rediA[w]; }
        pathA[63] = s;
        for (int t = 63; t >= 1; --t) {
            int g = s >> 2;
            int j = bp[t][g] & 3;
            s = g + (j << 8);                // prev = (s>>2) + j*HI, HI = 256
            pathA[t - 1] = s;
        }
    }
    if (k == 32) {
        float m = redvB[0]; int s = rediB[0];
#pragma unroll
        for (int w = 1; w < 8; ++w)
            if (redvB[w] < m || (redvB[w] == m && rediB[w] < s)) { m = redvB[w]; s = rediB[w]; }
        pathB[63] = s;
        for (int t = 63; t >= 1; --t) {
            int g = s >> 2;
            int j = (bp[t][g] >> 2) & 3;
            s = g + (j << 8);
            pathB[t - 1] = s;
        }
    }
    __syncthreads();

    // ---- emit: rec (exact codebook gather) + states, both blocks ----
    if (k < 128) {
        int t = k & 63;
        bool isB = k >= 64;
        int s = isB ? pathB[t] : pathA[t];
        int bb = isB ? bB : bA;
        int br = isB ? brB : brA;
        int bc = isB ? bcB : bcA;
        float4 val = __ldg(cb4 + s);
        int row = br * 16 + (t >> 2);
        int col = bc * 16 + ((t & 3) << 2);
        reinterpret_cast<float4*>(out + row * ROWS + col)[0] = val;
        int sidx = ROWS * ROWS + bb * 64 + t;
        if (sidx < out_size) out[sidx] = (float)s;
    }
}

} // namespace

extern "C" void kernel_launch(void* const* d_in, const int* in_sizes, int n_in,
                              void* d_out, int out_size) {
    const float* array    = (const float*)d_in[0];
    const float* codebook = (const float*)d_in[1];
    (void)in_sizes; (void)n_in;
    float* out = (float*)d_out;
    viterbi_kernel<<<NCTA, NTH>>>(array, codebook, out, out_size);
}

// round 13
// speedup vs baseline: 1.0377x; 1.0199x over previous
#include <cuda_runtime.h>
#include <cstdint>

namespace {

constexpr int NTH  = 128;    // thread k owns groups 2k, 2k+1 (states 8k..8k+7)
constexpr int NCTA = 2048;   // each CTA handles 2 data blocks
constexpr int ROWS = 1024;

__device__ __forceinline__ float costf(const float4 cb, float cn, const float4 x) {
    return fmaf(cb.w, x.w, fmaf(cb.z, x.z, fmaf(cb.y, x.y, fmaf(cb.x, x.x, cn))));
}
__device__ __forceinline__ float cnrm(const float4 c) {
    return fmaf(c.w, c.w, fmaf(c.z, c.z, fmaf(c.y, c.y, c.x * c.x)));
}
// min-of-4 with index in the 2 mantissa LSBs (validated rel_err 0.0 in R11/R12)
__device__ __forceinline__ float min4_lsb(float a0, float a1, float a2, float a3) {
    float p0 = __uint_as_float((__float_as_uint(a0) & ~3u) | 0u);
    float p1 = __uint_as_float((__float_as_uint(a1) & ~3u) | 1u);
    float p2 = __uint_as_float((__float_as_uint(a2) & ~3u) | 2u);
    float p3 = __uint_as_float((__float_as_uint(a3) & ~3u) | 3u);
    return fminf(fminf(p0, p1), fminf(p2, p3));
}

__global__ __launch_bounds__(NTH, 6)
void viterbi_kernel(const float* __restrict__ array,
                    const float* __restrict__ codebook,
                    float* __restrict__ out,
                    int out_size)
{
    __shared__ float gA[2][256], gB[2][256];     // group-min state (ping-pong)
    __shared__ float4 xsA[64], xsB[64];
    __shared__ unsigned char bp[64][NTH];        // jA0|jA1<<2|jB0<<4|jB1<<6
    __shared__ int   pathA[64], pathB[64];
    __shared__ float redvA[4], redvB[4];
    __shared__ int   rediA[4], rediB[4];

    const int k  = threadIdx.x;                  // 0..127
    const int bA = 2 * blockIdx.x;
    const int bB = bA + 1;
    const int brA = bA >> 6, bcA = bA & 63;
    const int brB = bB >> 6, bcB = bB & 63;

    // ---- load both blocks' 256 elements each, pre-scaled by -2 ----
#pragma unroll
    for (int e = k; e < 256; e += NTH) {
        int r = e >> 4, cc = e & 15;
        float vA = array[(brA * 16 + r) * ROWS + (bcA * 16 + cc)];
        float vB = array[(brB * 16 + r) * ROWS + (bcB * 16 + cc)];
        reinterpret_cast<float*>(xsA)[e] = -2.0f * vA;
        reinterpret_cast<float*>(xsB)[e] = -2.0f * vB;
    }

    // ---- candidate cb rows for groups ga=2k, gb=2k+1: g + 256j ----
    const float4* cb4 = reinterpret_cast<const float4*>(codebook);
    const int ga = 2 * k, gb = 2 * k + 1;
    float4 p0 = __ldg(cb4 + ga + 0),   q0 = __ldg(cb4 + gb + 0);
    float4 p1 = __ldg(cb4 + ga + 256), q1 = __ldg(cb4 + gb + 256);
    float4 p2 = __ldg(cb4 + ga + 512), q2 = __ldg(cb4 + gb + 512);
    float4 p3 = __ldg(cb4 + ga + 768), q3 = __ldg(cb4 + gb + 768);
    float pn0 = cnrm(p0), pn1 = cnrm(p1), pn2 = cnrm(p2), pn3 = cnrm(p3);
    float qn0 = cnrm(q0), qn1 = cnrm(q1), qn2 = cnrm(q2), qn3 = cnrm(q3);

    __syncthreads();

    // ---- G_0 for both groups, both blocks (free initial state) ----
    float mAa, mAb, mBa, mBb;                    // G for (blockA,ga),(A,gb),(B,ga),(B,gb)
    {
        float4 xA = xsA[0], xB = xsB[0];
        mAa = min4_lsb(costf(p0, pn0, xA), costf(p1, pn1, xA), costf(p2, pn2, xA), costf(p3, pn3, xA));
        mAb = min4_lsb(costf(q0, qn0, xA), costf(q1, qn1, xA), costf(q2, qn2, xA), costf(q3, qn3, xA));
        mBa = min4_lsb(costf(p0, pn0, xB), costf(p1, pn1, xB), costf(p2, pn2, xB), costf(p3, pn3, xB));
        mBb = min4_lsb(costf(q0, qn0, xB), costf(q1, qn1, xB), costf(q2, qn2, xB), costf(q3, qn3, xB));
        bp[1][k] = (unsigned char)((__float_as_uint(mAa) & 3u)        |
                                   ((__float_as_uint(mAb) & 3u) << 2) |
                                   ((__float_as_uint(mBa) & 3u) << 4) |
                                   ((__float_as_uint(mBb) & 3u) << 6));
        *reinterpret_cast<float2*>(&gA[0][ga]) = make_float2(mAa, mAb);
        *reinterpret_cast<float2*>(&gB[0][ga]) = make_float2(mBa, mBb);
    }
    __syncthreads();

    // ---- recursion on G: both groups share predecessor base k>>1 ----
    const int base = k >> 1;
#pragma unroll 4
    for (int t = 1; t <= 62; ++t) {
        const float* gpA = gA[(t + 1) & 1];
        const float* gpB = gB[(t + 1) & 1];
        // 1) shared G reads (serve both groups)
        float a0 = gpA[base], a1 = gpA[base + 64], a2 = gpA[base + 128], a3 = gpA[base + 192];
        float b0 = gpB[base], b1 = gpB[base + 64], b2 = gpB[base + 128], b3 = gpB[base + 192];

        // 2) barrier-independent cost chains (4 chains x 4 rows)
        float4 xA = xsA[t], xB = xsB[t];
        float cAa0 = costf(p0, pn0, xA), cAa1 = costf(p1, pn1, xA), cAa2 = costf(p2, pn2, xA), cAa3 = costf(p3, pn3, xA);
        float cAb0 = costf(q0, qn0, xA), cAb1 = costf(q1, qn1, xA), cAb2 = costf(q2, qn2, xA), cAb3 = costf(q3, qn3, xA);
        float cBa0 = costf(p0, pn0, xB), cBa1 = costf(p1, pn1, xB), cBa2 = costf(p2, pn2, xB), cBa3 = costf(p3, pn3, xB);
        float cBb0 = costf(q0, qn0, xB), cBb1 = costf(q1, qn1, xB), cBb2 = costf(q2, qn2, xB), cBb3 = costf(q3, qn3, xB);

        // 3) candidates + LSB argmin, 4 independent chains
        mAa = min4_lsb(a0 + cAa0, a1 + cAa1, a2 + cAa2, a3 + cAa3);
        mAb = min4_lsb(a0 + cAb0, a1 + cAb1, a2 + cAb2, a3 + cAb3);
        mBa = min4_lsb(b0 + cBa0, b1 + cBa1, b2 + cBa2, b3 + cBa3);
        mBb = min4_lsb(b0 + cBb0, b1 + cBb1, b2 + cBb2, b3 + cBb3);
        bp[t + 1][k] = (unsigned char)((__float_as_uint(mAa) & 3u)        |
                                       ((__float_as_uint(mAb) & 3u) << 2) |
                                       ((__float_as_uint(mBa) & 3u) << 4) |
                                       ((__float_as_uint(mBb) & 3u) << 6));
        *reinterpret_cast<float2*>(&gA[t & 1][ga]) = make_float2(mAa, mAb);
        *reinterpret_cast<float2*>(&gB[t & 1][ga]) = make_float2(mBa, mBb);
        __syncthreads();
    }

    // ---- epilogue: alpha_63[s] = G_62[s>>2] + cost_63(s), s = 8k..8k+7 ----
    float4 xA = xsA[63], xB = xsB[63];
    float vA[8], vB[8];
#pragma unroll
    for (int c = 0; c < 8; ++c) {
        float4 oc = __ldg(cb4 + 8 * k + c);
        float onc = cnrm(oc);
        float gAv = (c < 4) ? mAa : mAb;
        float gBv = (c < 4) ? mBa : mBb;
        vA[c] = gAv + costf(oc, onc, xA);
        vB[c] = gBv + costf(oc, onc, xB);
    }

    // ---- final argmin over 1024 states, first-occurrence ----
    {
        float bm = vA[0]; int bi = 8 * k;
        float cm = vB[0]; int ci = 8 * k;
#pragma unroll
        for (int c = 1; c < 8; ++c) {
            if (vA[c] < bm) { bm = vA[c]; bi = 8 * k + c; }
            if (vB[c] < cm) { cm = vB[c]; ci = 8 * k + c; }
        }
#pragma unroll
        for (int off = 16; off; off >>= 1) {
            float om = __shfl_down_sync(0xffffffffu, bm, off);
            int   oi = __shfl_down_sync(0xffffffffu, bi, off);
            if (om < bm || (om == bm && oi < bi)) { bm = om; bi = oi; }
            float pm = __shfl_down_sync(0xffffffffu, cm, off);
            int   pi = __shfl_down_sync(0xffffffffu, ci, off);
            if (pm < cm || (pm == cm && pi < ci)) { cm = pm; ci = pi; }
        }
        if ((k & 31) == 0) {
            redvA[k >> 5] = bm; rediA[k >> 5] = bi;
            redvB[k >> 5] = cm; rediB[k >> 5] = ci;
        }
    }
    __syncthreads();

    // ---- backtrack: thread 0 does A, thread 32 does B ----
    if (k == 0) {
        float m = redvA[0]; int s = rediA[0];
#pragma unroll
        for (int w = 1; w < 4; ++w)
            if (redvA[w] < m || (redvA[w] == m && rediA[w] < s)) { m = redvA[w]; s = rediA[w]; }
        pathA[63] = s;
        for (int t = 63; t >= 1; --t) {
            int g = s >> 2;
            int j = (bp[t][g >> 1] >> (2 * (g & 1))) & 3;
            s = g + (j << 8);                    // prev = (s>>2) + j*256
            pathA[t - 1] = s;
        }
    }
    if (k == 32) {
        float m = redvB[0]; int s = rediB[0];
#pragma unroll
        for (int w = 1; w < 4; ++w)
            if (redvB[w] < m || (redvB[w] == m && rediB[w] < s)) { m = redvB[w]; s = rediB[w]; }
        pathB[63] = s;
        for (int t = 63; t >= 1; --t) {
            int g = s >> 2;
            int j = (bp[t][g >> 1] >> (4 + 2 * (g & 1))) & 3;
            s = g + (j << 8);
            pathB[t - 1] = s;
        }
    }
    __syncthreads();

    // ---- emit: rec (exact codebook gather) + states, both blocks ----
    {
        int t = k & 63;
        bool isB = k >= 64;
        int s = isB ? pathB[t] : pathA[t];
        int bb = isB ? bB : bA;
        int br = isB ? brB : brA;
        int bc = isB ? bcB : bcA;
        float4 val = __ldg(cb4 + s);
        int row = br * 16 + (t >> 2);
        int col = bc * 16 + ((t & 3) << 2);
        reinterpret_cast<float4*>(out + row * ROWS + col)[0] = val;
        int sidx = ROWS * ROWS + bb * 64 + t;
        if (sidx < out_size) out[sidx] = (float)s;
    }
}

} // namespace

extern "C" void kernel_launch(void* const* d_in, const int* in_sizes, int n_in,
                              void* d_out, int out_size) {
    const float* array    = (const float*)d_in[0];
    const float* codebook = (const float*)d_in[1];
    (void)in_sizes; (void)n_in;
    float* out = (float*)d_out;
    viterbi_kernel<<<NCTA, NTH>>>(array, codebook, out, out_size);
}